// round 15
// baseline (speedup 1.0000x reference)
#include <cuda_runtime.h>
#include <cuda_bf16.h>
#include <cstdint>
#include <cstring>

// involution: B=4, C=256, G=16, K=7, S=1, P=3, R=4, H=W=56
#define BB    4
#define CC    256
#define GG    16
#define CPG   16
#define KF    7
#define PAD   3
#define HH    56
#define WW    56
#define SP    3136            // H*W
#define P_TOT 12544           // B*H*W
#define CR    64              // C/R
#define KK    49
#define KKG   784             // K*K*G
#define TW    28
#define XWW   36

// ---------------- device scratch ----------------
__device__ float g_kern[KKG * P_TOT];                // 39.3 MB (L2-resident)
__device__ __align__(16) uint4 g_A[2][196][32];      // sw bf16 hi/lo A-fragments

__device__ __forceinline__ unsigned short bfbits(__nv_bfloat16 h) {
    unsigned short s; memcpy(&s, &h, 2); return s;
}
__device__ __forceinline__ void mma_bf16(float* c, const uint4& a,
                                         unsigned b0, unsigned b1) {
    asm volatile(
        "mma.sync.aligned.m16n8k16.row.col.f32.bf16.bf16.f32 "
        "{%0,%1,%2,%3}, {%4,%5,%6,%7}, {%8,%9}, {%0,%1,%2,%3};"
        : "+f"(c[0]), "+f"(c[1]), "+f"(c[2]), "+f"(c[3])
        : "r"(a.x), "r"(a.y), "r"(a.z), "r"(a.w), "r"(b0), "r"(b1));
}

// ---------------- prep: split sw into bf16 hi/lo A-fragments ----------------
__global__ void prep_sw_kernel(const float* __restrict__ sw)
{
    int i = blockIdx.x * blockDim.x + threadIdx.x;
    if (i >= 196 * 32) return;
    int tu = i >> 5, lane = i & 31;
    int t = tu >> 2, u = tu & 3;
    int r0 = t * 16 + (lane >> 2);
    int c0 = u * 16 + (lane & 3) * 2;
    const int rr[4] = {r0, r0 + 8, r0, r0 + 8};
    const int cc[4] = {c0, c0, c0 + 8, c0 + 8};
    unsigned hv[4], lv[4];
    #pragma unroll
    for (int j = 0; j < 4; j++) {
        float v0 = sw[rr[j] * CR + cc[j]];
        float v1 = sw[rr[j] * CR + cc[j] + 1];
        __nv_bfloat16 h0 = __float2bfloat16(v0);
        __nv_bfloat16 h1 = __float2bfloat16(v1);
        __nv_bfloat16 l0 = __float2bfloat16(v0 - __bfloat162float(h0));
        __nv_bfloat16 l1 = __float2bfloat16(v1 - __bfloat162float(h1));
        hv[j] = (unsigned)bfbits(h0) | ((unsigned)bfbits(h1) << 16);
        lv[j] = (unsigned)bfbits(l0) | ((unsigned)bfbits(l1) << 16);
    }
    g_A[0][tu][lane] = make_uint4(hv[0], hv[1], hv[2], hv[3]);
    g_A[1][tu][lane] = make_uint4(lv[0], lv[1], lv[2], lv[3]);
}

// ---------------- K12: h = rw@x+rb (scalar) -> smem panels -> HMMA -> g_kern
#define HSB       72
#define RW_F      16384
#define XS_F      8192
#define K12_SMEM  ((RW_F + XS_F) * 4 + 2 * 32 * HSB * 2)   // 107520 B
__global__ __launch_bounds__(256, 2)
void k12_gen(const float* __restrict__ x,
             const float* __restrict__ rw,
             const float* __restrict__ rb,
             const float* __restrict__ sb)
{
    extern __shared__ float sm1[];
    float*  rws  = sm1;                          // [64][256]
    float*  xs   = sm1 + RW_F;                   // [256][32]
    __nv_bfloat16* hb = (__nv_bfloat16*)(sm1 + RW_F + XS_F);   // [32][72]
    __nv_bfloat16* lb = hb + 32 * HSB;                          // [32][72]
    float4* rws4 = (float4*)rws;
    float4* xs4  = (float4*)xs;

    const int tid  = threadIdx.x;
    const int warp = tid >> 5;
    const int lane = tid & 31;
    const int p0   = blockIdx.x * 32;
    const int b    = p0 / SP;
    const int s0   = p0 - b * SP;
    const int o0   = warp * 8;

    {
        const float4* rwg4 = (const float4*)rw;
        #pragma unroll
        for (int i = tid; i < RW_F / 4; i += 256) rws4[i] = rwg4[i];
        const float* xb = x + (size_t)(b * CC) * SP + s0;
        #pragma unroll
        for (int i = tid; i < XS_F / 4; i += 256) {
            int c = i >> 3, q = i & 7;
            xs4[i] = *(const float4*)(xb + (size_t)c * SP + q * 4);
        }
    }
    __syncthreads();

    float acc[8];
    #pragma unroll
    for (int j = 0; j < 8; j++) acc[j] = 0.f;

    #pragma unroll 4
    for (int cq = 0; cq < 64; cq++) {
        float4 w[8];
        #pragma unroll
        for (int j = 0; j < 8; j++) w[j] = rws4[(o0 + j) * 64 + cq];
        #pragma unroll
        for (int e = 0; e < 4; e++) {
            float xv = xs[(cq * 4 + e) * 32 + lane];
            #pragma unroll
            for (int j = 0; j < 8; j++) {
                float we = (e == 0) ? w[j].x : (e == 1) ? w[j].y
                         : (e == 2) ? w[j].z : w[j].w;
                acc[j] += we * xv;
            }
        }
    }
    #pragma unroll
    for (int j = 0; j < 8; j++) {
        float v = acc[j] + __ldg(rb + o0 + j);
        __nv_bfloat16 h = __float2bfloat16(v);
        hb[lane * HSB + o0 + j] = h;
        lb[lane * HSB + o0 + j] = __float2bfloat16(v - __bfloat162float(h));
    }
    __syncthreads();

    #pragma unroll 1
    for (int t = warp; t < 49; t += 8) {
        uint4 ah[4], al[4];
        #pragma unroll
        for (int u = 0; u < 4; u++) {
            ah[u] = g_A[0][t * 4 + u][lane];
            al[u] = g_A[1][t * 4 + u][lane];
        }
        const int r0 = t * 16 + (lane >> 2);
        const float bias0 = __ldg(sb + r0);
        const float bias1 = __ldg(sb + r0 + 8);

        float facc[4][4];
        #pragma unroll
        for (int v = 0; v < 4; v++) {
            facc[v][0] = bias0; facc[v][1] = bias0;
            facc[v][2] = bias1; facc[v][3] = bias1;
        }
        #pragma unroll
        for (int v = 0; v < 4; v++) {
            const int n = v * 8 + (lane >> 2);
            const __nv_bfloat16* hrow = hb + n * HSB;
            const __nv_bfloat16* lrow = lb + n * HSB;
            #pragma unroll
            for (int u = 0; u < 4; u++) {
                const int k0 = u * 16 + (lane & 3) * 2;
                unsigned bh0 = *(const unsigned*)(hrow + k0);
                unsigned bh1 = *(const unsigned*)(hrow + k0 + 8);
                unsigned bl0 = *(const unsigned*)(lrow + k0);
                unsigned bl1 = *(const unsigned*)(lrow + k0 + 8);
                mma_bf16(facc[v], ah[u], bh0, bh1);
                mma_bf16(facc[v], ah[u], bl0, bl1);
                mma_bf16(facc[v], al[u], bh0, bh1);
            }
        }
        #pragma unroll
        for (int v = 0; v < 4; v++) {
            const int px0 = v * 8 + (lane & 3) * 2;
            *(float2*)(g_kern + (size_t)r0 * P_TOT + p0 + px0) =
                make_float2(facc[v][0], facc[v][1]);
            *(float2*)(g_kern + (size_t)(r0 + 8) * P_TOT + p0 + px0) =
                make_float2(facc[v][2], facc[v][3]);
        }
    }
}

// ---------------- K3: involution apply, row-pair tiles ----------------------
// grid (2, 28, 4) = 224 blocks, 256 thr = 8 warps.
// Each warp: group g = 8s+w; per channel fill an 8-row x 36-col window (rows
// y0-3 .. y0+4) and produce output rows y0, y0+1. Double-buffered per warp.
#define WROWS 8
#define WFL   (WROWS * XWW)          // 288 floats per window
#define WQ2   (WFL / 4)              // 72 quads
#define K3_SMEM (8 * 2 * WFL * 4)    // 18432 B
__global__ __launch_bounds__(256, 2)
void k3_apply(const float* __restrict__ x, float* __restrict__ out)
{
    extern __shared__ float sm3[];
    const int tid  = threadIdx.x;
    const int warp = tid >> 5;
    const int lane = tid & 31;
    const int x0   = blockIdx.x * TW;
    const int y0   = blockIdx.y * 2;
    const int b    = blockIdx.z;

    float* wbase = sm3 + warp * (2 * WFL);

    // fill slots: quads i = lane, lane+32, lane+64 (lane<8)
    int  fy[3], fc[3];
    bool fok[3];
    #pragma unroll
    for (int t = 0; t < 3; t++) {
        int i  = lane + 32 * t;
        int r  = i / (XWW / 4);
        int q  = i - r * (XWW / 4);
        fy[t]  = y0 + r - PAD;                 // r=0..7 -> y0-3 .. y0+4
        fc[t]  = x0 - 4 + q * 4;
        fok[t] = (i < WQ2) && ((unsigned)fy[t] < HH) && ((unsigned)fc[t] < WW);
    }

    const int pcol0 = b * SP + y0 * WW + x0 + lane;

    #pragma unroll 1
    for (int s = 0; s < 2; s++) {
        const int g = 8 * s + warp;

        float kr0[KK], kr1[KK];
        if (lane < TW) {
            const float* kb = g_kern + (size_t)(g * KK) * P_TOT + pcol0;
            #pragma unroll
            for (int t = 0; t < KK; t++) {
                kr0[t] = kb[(size_t)t * P_TOT];
                kr1[t] = kb[(size_t)t * P_TOT + WW];
            }
        }

        const int cbase = g * CPG;
        float4 pf[3];
        #pragma unroll
        for (int t = 0; t < 3; t++) pf[t] = make_float4(0.f, 0.f, 0.f, 0.f);
        {
            const float* xr = x + (size_t)(b * CC + cbase) * SP;
            #pragma unroll
            for (int t = 0; t < 3; t++)
                if (fok[t]) pf[t] = *(const float4*)(xr + fy[t] * WW + fc[t]);
        }

        #pragma unroll 1
        for (int ci = 0; ci < CPG; ci++) {
            float*  buf  = wbase + (ci & 1) * WFL;
            float4* buf4 = (float4*)buf;
            buf4[lane]      = pf[0];
            buf4[lane + 32] = pf[1];
            if (lane < WQ2 - 64) buf4[lane + 64] = pf[2];
            __syncwarp();

            if (ci + 1 < CPG) {
                const float* xr = x + (size_t)(b * CC + cbase + ci + 1) * SP;
                #pragma unroll
                for (int t = 0; t < 3; t++)
                    pf[t] = fok[t] ? *(const float4*)(xr + fy[t] * WW + fc[t])
                                   : make_float4(0.f, 0.f, 0.f, 0.f);
            }

            if (lane < TW) {
                const float* wrow = buf + lane + 1;
                float a0 = 0.f, a1 = 0.f;   // row y0
                float b0 = 0.f, b1 = 0.f;   // row y0+1
                #pragma unroll
                for (int r = 0; r < KF; r++) {
                    #pragma unroll
                    for (int kw = 0; kw < KF; kw++) {
                        float v0 = wrow[r * XWW + kw];           // window row r
                        float v1 = wrow[(r + 1) * XWW + kw];     // window row r+1
                        float w0 = kr0[r * KF + kw];
                        float w1 = kr1[r * KF + kw];
                        if (kw & 1) { a1 += w0 * v0; b1 += w1 * v1; }
                        else        { a0 += w0 * v0; b0 += w1 * v1; }
                    }
                }
                const size_t obase = (size_t)(b * CC + cbase + ci) * SP
                                   + y0 * WW + x0 + lane;
                out[obase]      = a0 + a1;
                out[obase + WW] = b0 + b1;
            }
            __syncwarp();   // WAR: buf reads done before next fill to same slot
        }
    }
}

// ---------------- launcher ----------------
extern "C" void kernel_launch(void* const* d_in, const int* in_sizes, int n_in,
                              void* d_out, int out_size)
{
    const float* x  = (const float*)d_in[0];  // (4,256,56,56)
    const float* rw = (const float*)d_in[1];  // (64,256)
    const float* rb = (const float*)d_in[2];  // (64,)
    const float* sw = (const float*)d_in[3];  // (784,64)
    const float* sb = (const float*)d_in[4];  // (784,)
    float* out = (float*)d_out;

    cudaFuncSetAttribute(k12_gen, cudaFuncAttributeMaxDynamicSharedMemorySize, K12_SMEM);
    cudaFuncSetAttribute(k3_apply, cudaFuncAttributeMaxDynamicSharedMemorySize, K3_SMEM);

    prep_sw_kernel<<<25, 256>>>(sw);
    k12_gen<<<P_TOT / 32, 256, K12_SMEM>>>(x, rw, rb, sb);
    k3_apply<<<dim3(WW / TW, HH / 2, BB), 256, K3_SMEM>>>(x, out);
}

// round 16
// speedup vs baseline: 1.6258x; 1.6258x over previous
#include <cuda_runtime.h>
#include <cuda_bf16.h>
#include <cstdint>
#include <cstring>

// involution: B=4, C=256, G=16, K=7, S=1, P=3, R=4, H=W=56
#define BB    4
#define CC    256
#define GG    16
#define CPG   16
#define KF    7
#define PAD   3
#define HH    56
#define WW    56
#define SP    3136            // H*W
#define P_TOT 12544           // B*H*W
#define CR    64              // C/R
#define KK    49
#define KKG   784             // K*K*G
#define TW    28
#define XWW   36
#define WQ    (KF * XWW / 4)  // 63 quads per window

#define NPREP 25              // leading blocks that run sw-conversion

// ---------------- device scratch ----------------
__device__ float g_kern[KKG * P_TOT];                // 39.3 MB (L2-resident)
__device__ __align__(16) uint4 g_A[2][196][32];      // sw bf16 hi/lo A-fragments
__device__ int g_ctr = 0;                            // monotonic prep-done counter

__device__ __forceinline__ unsigned short bfbits(__nv_bfloat16 h) {
    unsigned short s; memcpy(&s, &h, 2); return s;
}
__device__ __forceinline__ void mma_bf16(float* c, const uint4& a,
                                         unsigned b0, unsigned b1) {
    asm volatile(
        "mma.sync.aligned.m16n8k16.row.col.f32.bf16.bf16.f32 "
        "{%0,%1,%2,%3}, {%4,%5,%6,%7}, {%8,%9}, {%0,%1,%2,%3};"
        : "+f"(c[0]), "+f"(c[1]), "+f"(c[2]), "+f"(c[3])
        : "r"(a.x), "r"(a.y), "r"(a.z), "r"(a.w), "r"(b0), "r"(b1));
}

// ---------------- K12: prep blocks + (reduce GEMM -> HMMA span GEMM) -------
// grid 221: blocks 0..24 convert sw into g_A; blocks 25..220 are 64-px tiles.
// tile smem: rws [64][256] f32 | xs [64 c][64 px] f32 | hb/lb [64][72] bf16
#define HSB       72
#define XS_F      16384
#define PAN_F     20480
#define K12_SMEM  (20480 * 4 + 2 * 64 * HSB * 2)    // 100352 B
__global__ __launch_bounds__(256, 2)
void k12_gen(const float* __restrict__ x,
             const float* __restrict__ rw,
             const float* __restrict__ rb,
             const float* __restrict__ sw,
             const float* __restrict__ sb)
{
    extern __shared__ float sm1[];
    const int tid  = threadIdx.x;
    const int warp = tid >> 5;
    const int lane = tid & 31;

    // ======== prep blocks: sw -> bf16 hi/lo A-fragments (R9-verified) ======
    if (blockIdx.x < NPREP) {
        int i = blockIdx.x * 256 + tid;
        if (i < 196 * 32) {
            int tu = i >> 5, ln = i & 31;
            int t = tu >> 2, u = tu & 3;
            int r0 = t * 16 + (ln >> 2);
            int c0 = u * 16 + (ln & 3) * 2;
            const int rr[4] = {r0, r0 + 8, r0, r0 + 8};
            const int cc[4] = {c0, c0, c0 + 8, c0 + 8};
            unsigned hv[4], lv[4];
            #pragma unroll
            for (int j = 0; j < 4; j++) {
                float v0 = sw[rr[j] * CR + cc[j]];
                float v1 = sw[rr[j] * CR + cc[j] + 1];
                __nv_bfloat16 h0 = __float2bfloat16(v0);
                __nv_bfloat16 h1 = __float2bfloat16(v1);
                __nv_bfloat16 l0 = __float2bfloat16(v0 - __bfloat162float(h0));
                __nv_bfloat16 l1 = __float2bfloat16(v1 - __bfloat162float(h1));
                hv[j] = (unsigned)bfbits(h0) | ((unsigned)bfbits(h1) << 16);
                lv[j] = (unsigned)bfbits(l0) | ((unsigned)bfbits(l1) << 16);
            }
            g_A[0][tu][ln] = make_uint4(hv[0], hv[1], hv[2], hv[3]);
            g_A[1][tu][ln] = make_uint4(lv[0], lv[1], lv[2], lv[3]);
        }
        __threadfence();      // publish g_A before signalling
        __syncthreads();
        if (tid == 0) atomicAdd(&g_ctr, 1);
        return;
    }

    // ======== tile blocks (R9 k12 verbatim, blk = blockIdx.x - NPREP) ======
    float*  rws  = sm1;                          // [64][256]
    float*  xs   = sm1 + XS_F;                   // [64 c][64 px]
    __nv_bfloat16* hb = (__nv_bfloat16*)(sm1 + PAN_F);   // [64][72]
    __nv_bfloat16* lb = hb + 64 * HSB;                   // [64][72]
    float4* rws4 = (float4*)rws;
    float4* xs4  = (float4*)xs;

    const int p0 = (blockIdx.x - NPREP) * 64;
    const int b  = p0 / SP;
    const int s0 = p0 - b * SP;          // 3136 % 64 == 0: no batch crossing
    const int o0 = warp * 8;

    {   // stage rw
        const float4* rwg4 = (const float4*)rw;
        #pragma unroll
        for (int i = tid; i < 4096; i += 256) rws4[i] = rwg4[i];
    }

    // ---- Phase A: scalar reduce GEMM ----
    float acc[8][2];
    #pragma unroll
    for (int j = 0; j < 8; j++) { acc[j][0] = 0.f; acc[j][1] = 0.f; }

    #pragma unroll 1
    for (int chunk = 0; chunk < 4; chunk++) {
        __syncthreads();                 // WAR on xs (chunk 0: rws ready too)
        {
            const float* xb = x + ((size_t)(b * CC + chunk * 64)) * SP + s0;
            #pragma unroll
            for (int i = tid; i < 1024; i += 256) {
                int c = i >> 4, q = i & 15;
                xs4[i] = *(const float4*)(xb + (size_t)c * SP + q * 4);
            }
        }
        __syncthreads();

        #pragma unroll 2
        for (int cq = 0; cq < 16; cq++) {
            float4 w[8];
            #pragma unroll
            for (int j = 0; j < 8; j++)
                w[j] = rws4[(o0 + j) * 64 + chunk * 16 + cq];
            #pragma unroll
            for (int e = 0; e < 4; e++) {
                int c = cq * 4 + e;
                float xa  = xs[c * 64 + lane];
                float xb2 = xs[c * 64 + lane + 32];
                #pragma unroll
                for (int j = 0; j < 8; j++) {
                    float we = (e == 0) ? w[j].x : (e == 1) ? w[j].y
                             : (e == 2) ? w[j].z : w[j].w;
                    acc[j][0] += we * xa;
                    acc[j][1] += we * xb2;
                }
            }
        }
    }

    // ---- write bf16 hi/lo panels (transposed [n px][k o]) ----
    #pragma unroll
    for (int j = 0; j < 8; j++) {
        float bias = __ldg(rb + o0 + j);
        float v0 = acc[j][0] + bias;
        float v1 = acc[j][1] + bias;
        __nv_bfloat16 h0 = __float2bfloat16(v0);
        __nv_bfloat16 h1 = __float2bfloat16(v1);
        hb[lane * HSB + o0 + j]        = h0;
        hb[(lane + 32) * HSB + o0 + j] = h1;
        lb[lane * HSB + o0 + j]        = __float2bfloat16(v0 - __bfloat162float(h0));
        lb[(lane + 32) * HSB + o0 + j] = __float2bfloat16(v1 - __bfloat162float(h1));
    }

    // ---- gate: all 25 prep blocks done (satisfied instantly on replays) ----
    if (tid == 0) {
        while (*((volatile int*)&g_ctr) < NPREP) { __nanosleep(64); }
    }
    __syncthreads();
    __threadfence();   // acquire: g_A visible

    // ---- Phase B: HMMA span GEMM -> g_kern ----
    #pragma unroll 1
    for (int t = warp; t < 49; t += 8) {
        uint4 ah[4], al[4];
        #pragma unroll
        for (int u = 0; u < 4; u++) {
            ah[u] = g_A[0][t * 4 + u][lane];
            al[u] = g_A[1][t * 4 + u][lane];
        }
        const int r0 = t * 16 + (lane >> 2);
        const float bias0 = __ldg(sb + r0);
        const float bias1 = __ldg(sb + r0 + 8);

        float facc[8][4];
        #pragma unroll
        for (int v = 0; v < 8; v++) {
            facc[v][0] = bias0; facc[v][1] = bias0;
            facc[v][2] = bias1; facc[v][3] = bias1;
        }

        #pragma unroll
        for (int v = 0; v < 8; v++) {
            const int n = v * 8 + (lane >> 2);
            const __nv_bfloat16* hrow = hb + n * HSB;
            const __nv_bfloat16* lrow = lb + n * HSB;
            #pragma unroll
            for (int u = 0; u < 4; u++) {
                const int k0 = u * 16 + (lane & 3) * 2;
                unsigned bh0 = *(const unsigned*)(hrow + k0);
                unsigned bh1 = *(const unsigned*)(hrow + k0 + 8);
                unsigned bl0 = *(const unsigned*)(lrow + k0);
                unsigned bl1 = *(const unsigned*)(lrow + k0 + 8);
                mma_bf16(facc[v], ah[u], bh0, bh1);
                mma_bf16(facc[v], ah[u], bl0, bl1);
                mma_bf16(facc[v], al[u], bh0, bh1);
            }
        }

        #pragma unroll
        for (int v = 0; v < 8; v++) {
            const int px0 = v * 8 + (lane & 3) * 2;
            *(float2*)(g_kern + (size_t)r0 * P_TOT + p0 + px0) =
                make_float2(facc[v][0], facc[v][1]);
            *(float2*)(g_kern + (size_t)(r0 + 8) * P_TOT + p0 + px0) =
                make_float2(facc[v][2], facc[v][3]);
        }
    }
}

// ---------------- K3: involution apply (R9 pipelined version, FROZEN) ------
#define K3_SMEM (8 * 2 * KF * XWW * 4)
__global__ __launch_bounds__(256, 3)
void k3_apply(const float* __restrict__ x, float* __restrict__ out)
{
    extern __shared__ float sm3[];
    const int tid  = threadIdx.x;
    const int warp = tid >> 5;
    const int lane = tid & 31;
    const int x0   = blockIdx.x * TW;
    const int y    = blockIdx.y;
    const int b    = blockIdx.z;

    float* wbase = sm3 + warp * (2 * KF * XWW);
    const int pcol = b * SP + y * WW + x0 + lane;

    const int i0 = lane;
    const int r0q = i0 / (XWW / 4), q0 = i0 - r0q * (XWW / 4);
    const int yy0 = y + r0q - PAD,  c00 = x0 - 4 + q0 * 4;
    const bool ok0 = ((unsigned)yy0 < HH) && ((unsigned)c00 < WW);
    const int i1 = lane + 32;
    const int r1q = i1 / (XWW / 4), q1 = i1 - r1q * (XWW / 4);
    const int yy1 = y + r1q - PAD,  c10 = x0 - 4 + q1 * 4;
    const bool ok1 = (i1 < WQ) && ((unsigned)yy1 < HH) && ((unsigned)c10 < WW);

    #pragma unroll 1
    for (int s = 0; s < 2; s++) {
        const int g = 8 * s + warp;

        float kr[KK];
        if (lane < TW) {
            const float* kb = g_kern + (size_t)(g * KK) * P_TOT + pcol;
            #pragma unroll
            for (int t = 0; t < KK; t++) kr[t] = kb[(size_t)t * P_TOT];
        }

        const int cbase = g * CPG;
        float4 pf0 = make_float4(0.f, 0.f, 0.f, 0.f), pf1 = pf0;
        {
            const float* xr = x + (size_t)(b * CC + cbase) * SP;
            if (ok0) pf0 = *(const float4*)(xr + yy0 * WW + c00);
            if (ok1) pf1 = *(const float4*)(xr + yy1 * WW + c10);
        }

        #pragma unroll 1
        for (int ci = 0; ci < CPG; ci++) {
            float*  buf  = wbase + (ci & 1) * (KF * XWW);
            float4* buf4 = (float4*)buf;
            buf4[i0] = pf0;
            if (i1 < WQ) buf4[i1] = pf1;
            __syncwarp();

            if (ci + 1 < CPG) {
                const float* xr = x + (size_t)(b * CC + cbase + ci + 1) * SP;
                pf0 = ok0 ? *(const float4*)(xr + yy0 * WW + c00)
                          : make_float4(0.f, 0.f, 0.f, 0.f);
                pf1 = ok1 ? *(const float4*)(xr + yy1 * WW + c10)
                          : make_float4(0.f, 0.f, 0.f, 0.f);
            }

            if (lane < TW) {
                const float* wrow = buf + lane + 1;
                float a0 = 0.f, a1 = 0.f;
                #pragma unroll
                for (int r = 0; r < KF; r++) {
                    #pragma unroll
                    for (int kw = 0; kw < KF; kw++) {
                        float v = wrow[r * XWW + kw];
                        if (kw & 1) a1 += kr[r * KF + kw] * v;
                        else        a0 += kr[r * KF + kw] * v;
                    }
                }
                out[(size_t)(b * CC + cbase + ci) * SP + y * WW + x0 + lane] = a0 + a1;
            }
        }
    }
}

// ---------------- launcher ----------------
extern "C" void kernel_launch(void* const* d_in, const int* in_sizes, int n_in,
                              void* d_out, int out_size)
{
    const float* x  = (const float*)d_in[0];  // (4,256,56,56)
    const float* rw = (const float*)d_in[1];  // (64,256)
    const float* rb = (const float*)d_in[2];  // (64,)
    const float* sw = (const float*)d_in[3];  // (784,64)
    const float* sb = (const float*)d_in[4];  // (784,)
    float* out = (float*)d_out;

    cudaFuncSetAttribute(k12_gen, cudaFuncAttributeMaxDynamicSharedMemorySize, K12_SMEM);
    cudaFuncSetAttribute(k3_apply, cudaFuncAttributeMaxDynamicSharedMemorySize, K3_SMEM);

    k12_gen<<<NPREP + P_TOT / 64, 256, K12_SMEM>>>(x, rw, rb, sw, sb);
    k3_apply<<<dim3(WW / TW, HH, BB), 256, K3_SMEM>>>(x, out);
}